// round 11
// baseline (speedup 1.0000x reference)
#include <cuda_runtime.h>
#include <cuda_fp16.h>
#include <cstdint>

#define DD 64
#define LL 128
#define KROWS 8192
#define MROWS 32
#define NBLK (KROWS/MROWS)   // 256 CTAs -> 2 per SM
#define NTHR 512

typedef unsigned int u32;

// smem byte offsets
#define SM_A0  0          // h buf0: 32 rows x 128B (fp16)
#define SM_A1  4096
#define SM_BH  8192       // W fp16 staging: 256 n-rows x 128B (32KB); reused for sWa/sWf
#define SM_X   40960      // x: 32 x 129 floats = 16512B
#define SM_CA  57472      // 256 floats
#define SM_CB  58496      // 256 floats
#define SM_RED 59520      // 128 floats
#define SM_FIN 60032      // 3*64 floats
#define SM_FLG 60800      // 4B
#define SM_TOT 60864

__device__ float g_acc[128];
__device__ unsigned int g_ctr = 0;

__device__ __forceinline__ float fexp(float x){
    x = fmaxf(fminf(x, 30.f), -30.f);
    return __expf(x);
}
__device__ __forceinline__ float sigf(float x){
    return __fdividef(1.0f, 1.0f + fexp(-x));
}
__device__ __forceinline__ float tanhp(float x){
    return 2.0f * __fdividef(1.0f, 1.0f + fexp(-2.0f*x)) - 1.0f;
}
__device__ __forceinline__ float tanha(float x){
    float r; asm("tanh.approx.f32 %0, %1;" : "=f"(r) : "f"(x)); return r;
}
__device__ __forceinline__ float siga(float x){
    return fmaf(0.5f, tanha(0.5f*x), 0.5f);
}

__device__ __forceinline__ void mma_fp16(float* c, const u32* a, const u32* b){
    asm volatile("mma.sync.aligned.m16n8k16.row.col.f32.f16.f16.f32 "
        "{%0,%1,%2,%3}, {%4,%5,%6,%7}, {%8,%9}, {%0,%1,%2,%3};\n"
        : "+f"(c[0]),"+f"(c[1]),"+f"(c[2]),"+f"(c[3])
        : "r"(a[0]),"r"(a[1]),"r"(a[2]),"r"(a[3]), "r"(b[0]),"r"(b[1]));
}

// ---------- single fused kernel, weight-stationary, 32 rows/CTA ----------
__global__ void __launch_bounds__(NTHR,1)
lstm_kernel(const float* __restrict__ x,
            const float* __restrict__ W_num,  const float* __restrict__ b_num,
            const float* __restrict__ W_ih,   const float* __restrict__ W_hh,
            const float* __restrict__ b_ih,   const float* __restrict__ b_hh,
            const float* __restrict__ W_aout, const float* __restrict__ b_aout,
            const float* __restrict__ W_fh,   const float* __restrict__ b_fh,
            const float* __restrict__ W_iouh, const float* __restrict__ b_iouh,
            const float* __restrict__ W_oout, const float* __restrict__ b_oout,
            float* __restrict__ out){
    extern __shared__ char sm[];
    const int tid  = threadIdx.x;
    const int wid  = tid >> 5;
    const int lane = tid & 31;
    const int g    = lane >> 2;      // group 0..7
    const int tq   = lane & 3;       // quad  0..3
    const int mtp  = wid & 1;        // m16 tile 0/1 (rows mtp*16..)
    const int wn   = wid >> 1;       // n 32-col chunk 0..7
    const u32 xorv = (u32)g << 4;
    const int r0   = blockIdx.x * MROWS;

    float* sXf = (float*)(sm + SM_X);
    float* sCa = (float*)(sm + SM_CA);
    float* sCb = (float*)(sm + SM_CB);
    float* sRd = (float*)(sm + SM_RED);

    // ---- per-CTA prep ----
    // Column order: n = wn2*32 + j*8 + c; gate = j; d = wn2*8 + c; W row = j*64 + d.
    if (tid < 256){
        int n = tid;
        int wn2 = n >> 5;
        int j = (n >> 3) & 3;
        int c = n & 7;
        int d  = wn2*8 + c;
        int wr = j*64 + d;
        float sa = 0.f, sc = 0.f;
        #pragma unroll 8
        for (int k = 0; k < DD; k++){
            float w = __ldg(W_ih + wr*(2*DD) + k);
            sa += w * __ldg(W_num + k);
            sc += w * __ldg(b_num + k);
        }
        sCa[n] = sa;
        sCb[n] = sc + __ldg(b_ih + wr) + __ldg(b_hh + wr);
        #pragma unroll 8
        for (int k = 0; k < DD; k++){
            float w = __ldg(W_hh + wr*DD + k);
            u32 off = (u32)n*128 + (u32)k*2;
            u32 sw  = off ^ (((u32)n & 7u) << 4);
            *(__half*)(sm + SM_BH + sw) = __float2half_rn(w);
        }
    }
    {
        uint4 z = make_uint4(0,0,0,0);
        uint4* da = (uint4*)(sm + SM_A0);
        for (int i = tid; i < 512; i += NTHR) da[i] = z;    // A0+A1 (8KB)
        for (int idx = tid; idx < MROWS*LL; idx += NTHR){
            int rr = idx >> 7, tt = idx & 127;
            sXf[rr*129 + tt] = x[(size_t)(r0 + rr)*LL + tt];
        }
        if (tid < 128) sRd[tid] = 0.f;
    }
    __syncthreads();

    // ---- stationary B fragments in registers ----
    u32 breg[4][4][2];
    {
        const char* Bh0 = sm + SM_BH + (size_t)((wn*32 + g) * 128);
        #pragma unroll
        for (int k4 = 0; k4 < 4; k4++){
            u32 o0 = ((u32)(32*k4 + 4*tq)) ^ xorv;
            u32 o8 = o0 ^ 16u;
            #pragma unroll
            for (int j = 0; j < 4; j++){
                breg[j][k4][0] = *(const u32*)(Bh0 + j*1024 + o0);
                breg[j][k4][1] = *(const u32*)(Bh0 + j*1024 + o8);
            }
        }
    }

    float creg[4];
    #pragma unroll
    for (int i = 0; i < 4; i++) creg[i] = 0.f;

    for (int t = 0; t < LL; t++){
        const char* Ah = sm + ((t & 1) ? SM_A1 : SM_A0);
        char* Aw = sm + ((t & 1) ? SM_A0 : SM_A1);
        const char* ArH = Ah + mtp*2048 + g*128;

        float acc[16];
        #pragma unroll
        for (int i = 0; i < 16; i++) acc[i] = 0.f;

        #pragma unroll
        for (int k4 = 0; k4 < 4; k4++){
            u32 o0 = ((u32)(32*k4 + 4*tq)) ^ xorv;
            u32 o8 = o0 ^ 16u;
            u32 a0[4];
            a0[0] = *(const u32*)(ArH +        o0);
            a0[1] = *(const u32*)(ArH + 1024 + o0);
            a0[2] = *(const u32*)(ArH +        o8);
            a0[3] = *(const u32*)(ArH + 1024 + o8);
            #pragma unroll
            for (int j = 0; j < 4; j++)
                mma_fp16(acc + j*4, a0, breg[j][k4]);
        }

        // ---- epilogue: gates -> (c,h), write h fp16 ----
        float2 aJ[4], cJ[4];
        #pragma unroll
        for (int j = 0; j < 4; j++){
            int nI = wn*32 + j*8 + 2*tq;
            aJ[j] = *(const float2*)(sCa + nI);
            cJ[j] = *(const float2*)(sCb + nI);
        }
        const u32 cbS = ((u32)(wn*16 + 4*tq)) ^ xorv;
        #pragma unroll
        for (int s = 0; s < 2; s++){
            int r = mtp*16 + g + s*8;
            float xv = sXf[r*129 + t];
            float h2[2];
            #pragma unroll
            for (int u = 0; u < 2; u++){
                int fi = s*2 + u;
                float gi = acc[ 0 + fi] + (u?aJ[0].y:aJ[0].x)*xv + (u?cJ[0].y:cJ[0].x);
                float gf = acc[ 4 + fi] + (u?aJ[1].y:aJ[1].x)*xv + (u?cJ[1].y:cJ[1].x);
                float gg = acc[ 8 + fi] + (u?aJ[2].y:aJ[2].x)*xv + (u?cJ[2].y:cJ[2].x);
                float go = acc[12 + fi] + (u?aJ[3].y:aJ[3].x)*xv + (u?cJ[3].y:cJ[3].x);
                int ci = s*2 + u;
                float c2 = siga(gf)*creg[ci] + siga(gi)*tanha(gg);
                creg[ci] = c2;
                h2[u] = siga(go)*tanha(c2);
            }
            __half b0 = __float2half_rn(h2[0]);
            __half b1 = __float2half_rn(h2[1]);
            u32 hp = (u32)__half_as_ushort(b0) | ((u32)__half_as_ushort(b1) << 16);
            *(u32*)(Aw + r*128 + cbS) = hp;
        }
        __syncthreads();
    }

    // ---- final per-CTA stage ----
    float* sHfin = (float*)(sm + SM_X);            // [row][d] stride 64 (8KB)
    float* sCst  = (float*)(sm + SM_X + 8192);     // (8KB)
    #pragma unroll
    for (int s = 0; s < 2; s++){
        #pragma unroll
        for (int u = 0; u < 2; u++){
            int r = mtp*16 + g + s*8;
            int d = wn*8 + 2*tq + u;
            u32 sw = ((u32)(2*d)) ^ xorv;
            float h = __half2float(*(const __half*)(sm + SM_A0 + r*128 + sw));
            sHfin[r*64 + d] = h;
            sCst [r*64 + d] = creg[s*2 + u];
        }
    }
    float* sWa = (float*)(sm + SM_BH);
    float* sWf = sWa + 4096;
    for (int i = tid; i < 4096; i += NTHR){ sWa[i] = W_aout[i]; sWf[i] = W_fh[i]; }
    __syncthreads();

    float* sHhat = (float*)(sm + SM_A0);           // [row][d] stride 64 (8KB = A0+A1)
    const int row = tid >> 4;                      // 0..31
    const int d0  = (tid & 15) << 2;               // 4 d's per thread
    #pragma unroll
    for (int jj = 0; jj < 4; jj++){
        int d = d0 + jj;
        float acc2 = __ldg(b_aout + d);
        #pragma unroll 8
        for (int e = 0; e < DD; e++) acc2 += sHfin[row*64 + e] * sWa[d*64 + e];
        sHhat[row*64 + d] = acc2;
        atomicAdd(&sRd[64 + d], acc2);
    }
    __syncthreads();
    #pragma unroll
    for (int jj = 0; jj < 4; jj++){
        int d = d0 + jj;
        float f = __ldg(b_fh + d);
        #pragma unroll 8
        for (int e = 0; e < DD; e++) f += sHhat[row*64 + e] * sWf[d*64 + e];
        atomicAdd(&sRd[d], sigf(f) * sCst[row*64 + d]);
    }
    __syncthreads();

    // ---- global reduction + last-CTA finisher ----
    if (tid < 128) atomicAdd(&g_acc[tid], sRd[tid]);
    __threadfence();
    __syncthreads();
    if (tid == 0){
        unsigned int rnk = atomicAdd(&g_ctr, 1);
        *(u32*)(sm + SM_FLG) = (rnk == NBLK - 1) ? 1u : 0u;
    }
    __syncthreads();
    if (*(const u32*)(sm + SM_FLG)){
        float* sfc = (float*)(sm + SM_FIN);
        float* shs = sfc + 64;
        float* sho = sfc + 128;
        if (tid < 64){ sfc[tid] = g_acc[tid]; shs[tid] = g_acc[64 + tid]; }
        __syncthreads();
        if (tid < 64){
            int d = tid;
            float vi = __ldg(b_iouh + d), vo = __ldg(b_iouh + 64 + d), vu = __ldg(b_iouh + 128 + d);
            #pragma unroll 8
            for (int e = 0; e < DD; e++){
                float h = shs[e];
                vi += h * __ldg(W_iouh + (      d)*64 + e);
                vo += h * __ldg(W_iouh + ( 64 + d)*64 + e);
                vu += h * __ldg(W_iouh + (128 + d)*64 + e);
            }
            float cobj = sigf(vi)*tanhp(vu) + sfc[d];
            sho[d] = sigf(vo)*tanhp(cobj);
            out[64 + d] = cobj;
        }
        __syncthreads();
        if (tid < 64){
            int d = tid;
            float acc3 = __ldg(b_oout + d);
            #pragma unroll 8
            for (int e = 0; e < DD; e++) acc3 += sho[e] * __ldg(W_oout + d*64 + e);
            out[d] = acc3;
        }
        if (tid < 128) g_acc[tid] = 0.f;
        __threadfence();
        if (tid == 0) g_ctr = 0;
    }
}

extern "C" void kernel_launch(void* const* d_in, const int* in_sizes, int n_in,
                              void* d_out, int out_size){
    const float* x      = (const float*)d_in[0];
    const float* W_num  = (const float*)d_in[1];
    const float* b_num  = (const float*)d_in[2];
    const float* W_ih   = (const float*)d_in[3];
    const float* W_hh   = (const float*)d_in[4];
    const float* b_ih   = (const float*)d_in[5];
    const float* b_hh   = (const float*)d_in[6];
    const float* W_aout = (const float*)d_in[7];
    const float* b_aout = (const float*)d_in[8];
    const float* W_fh   = (const float*)d_in[9];
    const float* b_fh   = (const float*)d_in[10];
    const float* W_iouh = (const float*)d_in[11];
    const float* b_iouh = (const float*)d_in[12];
    const float* W_oout = (const float*)d_in[13];
    const float* b_oout = (const float*)d_in[14];
    float* out = (float*)d_out;

    cudaFuncSetAttribute(lstm_kernel, cudaFuncAttributeMaxDynamicSharedMemorySize, SM_TOT);

    lstm_kernel<<<NBLK, NTHR, SM_TOT>>>(x, W_num, b_num, W_ih, W_hh, b_ih, b_hh,
                                        W_aout, b_aout, W_fh, b_fh,
                                        W_iouh, b_iouh, W_oout, b_oout, out);
}